// round 2
// baseline (speedup 1.0000x reference)
#include <cuda_runtime.h>
#include <math.h>

#define BB 32
#define CC 16
#define HH 256
#define WW 256
#define NOBJ 16
#define HW (HH*WW)

__device__ double g_base_sum;
__device__ double g_spatial_sum;
__device__ int    g_count[BB];

__global__ void scl_zero_kernel() {
    if (threadIdx.x == 0) { g_base_sum = 0.0; g_spatial_sum = 0.0; }
    if (threadIdx.x < BB) g_count[threadIdx.x] = 0;
}

// grid: (HW/(4*256), BB), block: 256 threads. Each thread: 4 consecutive pixels (float4).
__global__ void __launch_bounds__(256, 4)
scl_main_kernel(const float* __restrict__ pred,
                const float* __restrict__ targ,
                const float* __restrict__ layout)
{
    const int b = blockIdx.y;

    __shared__ int sxs[NOBJ], sxe[NOBJ], sys[NOBJ], sye[NOBJ];
    if (threadIdx.x < NOBJ) {
        const float* L = layout + ((size_t)b * NOBJ + threadIdx.x) * 4;
        float x = L[0], y = L[1], w = L[2], h = L[3];
        bool valid = (x > 0.0f) && (y > 0.0f);
        int xs = (int)floorf(x * WW);
        int ys = (int)floorf(y * HH);
        int xe = (int)floorf((x + w) * WW);
        int ye = (int)floorf((y + h) * HH);
        if (!valid) { xs = 0; xe = 0; ys = 0; ye = 0; }
        sxs[threadIdx.x] = xs; sxe[threadIdx.x] = xe;
        sys[threadIdx.x] = ys; sye[threadIdx.x] = ye;
    }
    __syncthreads();

    const int pix4    = blockIdx.x * blockDim.x + threadIdx.x; // float4 group index
    const int basepix = pix4 * 4;
    const int hrow    = basepix / WW;
    const int wcol0   = basepix % WW;

    const size_t off0 = (size_t)b * CC * HW + basepix;

    // ---- front-batched loads: all 32 LDG.128 issued before any consumption ----
    float4 pv[CC], tv[CC];
#pragma unroll
    for (int c = 0; c < CC; ++c)
        pv[c] = __ldg((const float4*)(pred + off0 + (size_t)c * HW));
#pragma unroll
    for (int c = 0; c < CC; ++c)
        tv[c] = __ldg((const float4*)(targ + off0 + (size_t)c * HW));

    float acc_sq = 0.0f;
    float a0 = 0.0f, a1 = 0.0f, a2 = 0.0f, a3 = 0.0f;

#pragma unroll
    for (int c = 0; c < CC; ++c) {
        float d0 = pv[c].x - tv[c].x;
        float d1 = pv[c].y - tv[c].y;
        float d2 = pv[c].z - tv[c].z;
        float d3 = pv[c].w - tv[c].w;
        acc_sq = fmaf(d0, d0, acc_sq);
        acc_sq = fmaf(d1, d1, acc_sq);
        acc_sq = fmaf(d2, d2, acc_sq);
        acc_sq = fmaf(d3, d3, acc_sq);
        a0 += fabsf(pv[c].x);
        a1 += fabsf(pv[c].y);
        a2 += fabsf(pv[c].z);
        a3 += fabsf(pv[c].w);
    }

    // Per-row object hit mask (same h for all 4 pixels)
    unsigned rowmask = 0u;
#pragma unroll
    for (int o = 0; o < NOBJ; ++o) {
        if (hrow >= sys[o] && hrow < sye[o]) rowmask |= (1u << o);
    }

    float sa[4] = { a0 * (1.0f/16.0f), a1 * (1.0f/16.0f),
                    a2 * (1.0f/16.0f), a3 * (1.0f/16.0f) };

    float acc_sp = 0.0f;
    int   cnt    = 0;
#pragma unroll
    for (int i = 0; i < 4; ++i) {
        const int wc = wcol0 + i;
        bool cov = false;
        unsigned m = rowmask;
        while (m) {
            int o = __ffs(m) - 1;
            m &= m - 1;
            if (wc >= sxs[o] && wc < sxe[o]) { cov = true; break; }
        }
        float ts = cov ? 1.0f : 0.0f;
        float d  = sa[i] - ts;
        acc_sp = fmaf(d, d, acc_sp);
        cnt += (sa[i] > 0.5f) ? 1 : 0;
    }

    // ---- block reduction ----
    const unsigned FULL = 0xFFFFFFFFu;
#pragma unroll
    for (int s = 16; s > 0; s >>= 1) {
        acc_sq += __shfl_down_sync(FULL, acc_sq, s);
        acc_sp += __shfl_down_sync(FULL, acc_sp, s);
        cnt    += __shfl_down_sync(FULL, cnt,    s);
    }

    __shared__ float s_sq[8], s_sp[8];
    __shared__ int   s_ct[8];
    const int lane = threadIdx.x & 31;
    const int wid  = threadIdx.x >> 5;
    if (lane == 0) { s_sq[wid] = acc_sq; s_sp[wid] = acc_sp; s_ct[wid] = cnt; }
    __syncthreads();

    if (wid == 0) {
        float bsq = (lane < 8) ? s_sq[lane] : 0.0f;
        float bsp = (lane < 8) ? s_sp[lane] : 0.0f;
        int   bct = (lane < 8) ? s_ct[lane] : 0;
#pragma unroll
        for (int s = 4; s > 0; s >>= 1) {
            bsq += __shfl_down_sync(FULL, bsq, s);
            bsp += __shfl_down_sync(FULL, bsp, s);
            bct += __shfl_down_sync(FULL, bct, s);
        }
        if (lane == 0) {
            atomicAdd(&g_base_sum,    (double)bsq);
            atomicAdd(&g_spatial_sum, (double)bsp);
            atomicAdd(&g_count[b],    bct);
        }
    }
}

__global__ void scl_finalize_kernel(const float* __restrict__ obj_counts,
                                    float* __restrict__ out)
{
    __shared__ float sh[BB];
    const int b = threadIdx.x;
    if (b < BB) {
        float d = (float)g_count[b] - obj_counts[b];
        sh[b] = d * d;
    }
    __syncthreads();
    if (b == 0) {
        float csum = 0.0f;
        for (int i = 0; i < BB; ++i) csum += sh[i];
        double base_loss    = g_base_sum    / ((double)BB * CC * HH * WW);
        double spatial_loss = g_spatial_sum / ((double)BB * HH * WW);
        double count_loss   = (double)csum  / (double)BB;
        out[0] = (float)(base_loss + spatial_loss + 0.5 * count_loss);
    }
}

extern "C" void kernel_launch(void* const* d_in, const int* in_sizes, int n_in,
                              void* d_out, int out_size)
{
    const float* pred   = (const float*)d_in[0];
    const float* targ   = (const float*)d_in[1];
    const float* layout = (const float*)d_in[2];
    const float* ocnt   = (const float*)d_in[3];
    float* out = (float*)d_out;

    scl_zero_kernel<<<1, 32>>>();
    dim3 grid(HW / (4 * 256), BB);
    scl_main_kernel<<<grid, 256>>>(pred, targ, layout);
    scl_finalize_kernel<<<1, BB>>>(ocnt, out);
}